// round 16
// baseline (speedup 1.0000x reference)
#include <cuda_runtime.h>
#include <cuda_bf16.h>
#include <cstdint>

#define NB       4096
#define NIN      41024
#define STG_F4   641               // float4 per stage
#define STGB     (STG_F4 * 16)     // 10256 bytes per stage
#define NSTGROW  32                // stages per fused row (16 w + 16 b)
#define NRING    3
#define NL1      128
#define NL2      32
#define CAPS     192
#define NT       256               // w0-5 scan (192t), w6 issuer, w7 consumer
#define NSCAN    192
#define NBLK     888               // 148 SMs * 6 resident blocks

__device__ __forceinline__ float clip01(float x) {
    return fminf(fmaxf(x, 0.f), 1.f);
}
__device__ __forceinline__ unsigned smem_u32(const void* p) {
    return (unsigned)__cvta_generic_to_shared(p);
}
__device__ __forceinline__ void mbar_init(unsigned a, unsigned cnt) {
    asm volatile("mbarrier.init.shared.b64 [%0], %1;" :: "r"(a), "r"(cnt) : "memory");
}
__device__ __forceinline__ void mbar_expect_tx(unsigned a, unsigned bytes) {
    asm volatile("mbarrier.arrive.expect_tx.shared.b64 _, [%0], %1;"
                 :: "r"(a), "r"(bytes) : "memory");
}
__device__ __forceinline__ void mbar_arrive(unsigned a) {
    asm volatile("mbarrier.arrive.shared.b64 _, [%0];" :: "r"(a) : "memory");
}
__device__ __forceinline__ void mbar_wait(unsigned a, unsigned phase) {
    asm volatile(
        "{\n\t.reg .pred P;\n\t"
        "W_%=:\n\t"
        "mbarrier.try_wait.parity.acquire.cta.shared::cta.b64 P, [%0], %1, 0x989680;\n\t"
        "@P bra.uni D_%=;\n\t"
        "bra.uni W_%=;\n\t"
        "D_%=:\n\t}"
        :: "r"(a), "r"(phase) : "memory");
}
__device__ __forceinline__ void tma_1d(unsigned dst, const void* src,
                                       unsigned bytes, unsigned mbar,
                                       unsigned long long pol) {
    asm volatile(
        "cp.async.bulk.shared::cluster.global.mbarrier::complete_tx::bytes.L2::cache_hint"
        " [%0], [%1], %2, [%3], %4;"
        :: "r"(dst), "l"(src), "r"(bytes), "r"(mbar), "l"(pol) : "memory");
}

// Event-driven TMA pipeline: warp 6 (lane 0) re-issues a ring slot the moment
// its empty barrier flips, keeping 3 stages/block outstanding at ALL times
// (26MB chip-wide -> HBM queue never drains; scan cadence no longer gates
// refill, fixing R15's lockstep bubble). Warps 0-5 scan stages from SMEM and
// compact nonzeros; warp 7 is the R6-proven consumer. Row handoff = named
// barrier (224 threads: scan+consumer) so the issuer free-runs across rows.
__global__ void __launch_bounds__(NT, 6) nnue_tma2_kernel(
    const float* __restrict__ us,   const float* __restrict__ them,
    const float* __restrict__ w_in, const float* __restrict__ b_in,
    const float* __restrict__ W_ft, const float* __restrict__ b_ft,
    const float* __restrict__ W1,   const float* __restrict__ b1,
    const float* __restrict__ W2,   const float* __restrict__ b2,
    const float* __restrict__ Wo,   const float* __restrict__ bo,
    float* __restrict__ out)
{
    __shared__ __align__(128) char s_stg[NRING][STGB];
    __shared__ __align__(8) unsigned long long s_full[NRING];
    __shared__ __align__(8) unsigned long long s_empty[NRING];
    __shared__ int   s_e[2][CAPS];      // (p<<16) | feature index
    __shared__ float s_v[2][CAPS];
    __shared__ int   s_cnt[2];
    __shared__ float s_l0[2 * NL1];     // consumer-private

    const int tid  = threadIdx.x;
    const int warp = tid >> 5;
    const int lane = tid & 31;
    const unsigned fullb  = smem_u32(&s_full[0]);
    const unsigned emptyb = smem_u32(&s_empty[0]);
    const unsigned stgb   = smem_u32(&s_stg[0][0]);

    if (tid == 0) {
        #pragma unroll
        for (int s = 0; s < NRING; ++s) {
            mbar_init(fullb + s * 8, 1);     // expect_tx arrival only
            mbar_init(emptyb + s * 8, 6);    // lane0 of each scan warp
        }
    }
    if (tid < 2) s_cnt[tid] = 0;
    __syncthreads();

    // rows handled by this block, stages total
    const int nr    = (NB - blockIdx.x + gridDim.x - 1) / gridDim.x;
    const int total = nr * NSTGROW;

    if (warp < 6) {
        // ==================== SCAN WARPS (0-5) ====================
        int k = 0;
        for (int i = 0; i < nr; ++i) {
            const int kb = i & 1;
            #pragma unroll 1
            for (int s = 0; s < NSTGROW; ++s, ++k) {
                const int slot = k % NRING;
                mbar_wait(fullb + slot * 8, (k / NRING) & 1);

                const float4* stg4 = (const float4*)(&s_stg[slot][0]);
                const int p    = s >> 4;
                const int rel0 = (s & 15) * STG_F4;
                const int tag  = p << 16;
                #pragma unroll 1
                for (int j = tid; j < STG_F4; j += NSCAN) {
                    const float4 vv = stg4[j];
                    // integer zero tests: mask values are {0.0f, 1.0f}
                    const int ix = __float_as_int(vv.x);
                    const int iy = __float_as_int(vv.y);
                    const int iz = __float_as_int(vv.z);
                    const int iw = __float_as_int(vv.w);
                    if ((ix | iy | iz | iw) != 0) {
                        const int col = (rel0 + j) * 4;
                        if (ix) { int q = atomicAdd(&s_cnt[kb], 1); if (q < CAPS) { s_e[kb][q] = tag | (col + 0); s_v[kb][q] = vv.x; } }
                        if (iy) { int q = atomicAdd(&s_cnt[kb], 1); if (q < CAPS) { s_e[kb][q] = tag | (col + 1); s_v[kb][q] = vv.y; } }
                        if (iz) { int q = atomicAdd(&s_cnt[kb], 1); if (q < CAPS) { s_e[kb][q] = tag | (col + 2); s_v[kb][q] = vv.z; } }
                        if (iw) { int q = atomicAdd(&s_cnt[kb], 1); if (q < CAPS) { s_e[kb][q] = tag | (col + 3); s_v[kb][q] = vv.w; } }
                    }
                }
                __syncwarp();
                if (lane == 0) mbar_arrive(emptyb + slot * 8);
            }
            asm volatile("bar.sync 1, 224;" ::: "memory");   // row handoff
        }
    } else if (warp == 6) {
        // ==================== ISSUER (warp 6, lane 0) ====================
        if (lane == 0) {
            unsigned long long pol;
            asm("createpolicy.fractional.L2::evict_first.b64 %0, 1.0;" : "=l"(pol));

            auto issue = [&](int ip) {
                const int j    = ip >> 5;                 // row index for block
                const int row  = blockIdx.x + j * (int)gridDim.x;
                const int s    = ip & 31;
                const int slot = ip % NRING;
                const float* src = (s < 16)
                    ? (w_in + (size_t)row * NIN + (size_t)s * (STG_F4 * 4))
                    : (b_in + (size_t)row * NIN + (size_t)(s - 16) * (STG_F4 * 4));
                mbar_expect_tx(fullb + slot * 8, STGB);
                tma_1d(stgb + slot * STGB, src, STGB, fullb + slot * 8, pol);
            };

            issue(0); issue(1); issue(2);
            #pragma unroll 1
            for (int k = NRING; k < total; ++k) {
                const int slot = k % NRING;
                const int t    = k / NRING;
                mbar_wait(emptyb + slot * 8, (t + 1) & 1);
                issue(k);
            }
        }
        // lanes 1-31 (and lane 0 when done) simply exit
    } else {
        // ==================== CONSUMER (warp 7) ====================
        int i = 0;
        for (int row = blockIdx.x; row < NB; row += gridDim.x, ++i) {
            asm volatile("bar.sync 1, 224;" ::: "memory");   // wait for row scan
            const int kb = i & 1;

            int cnt;
            if (lane == 0) { cnt = s_cnt[kb]; s_cnt[kb] = 0; }   // latch + reset
            cnt = min(__shfl_sync(0xffffffffu, cnt, 0), CAPS);

            // Gather: lane owns dims lane, lane+32, lane+64, lane+96.
            float aw0 = 0.f, aw1 = 0.f, aw2 = 0.f, aw3 = 0.f;
            float ab0 = 0.f, ab1 = 0.f, ab2 = 0.f, ab3 = 0.f;
            #pragma unroll 4
            for (int f = 0; f < cnt; ++f) {
                const int   e   = s_e[kb][f];
                const float val = s_v[kb][f];
                const float* wr = W_ft + (e & 0xFFFF) * NL1 + lane;
                const float w0 = __ldg(wr);
                const float w1 = __ldg(wr + 32);
                const float w2 = __ldg(wr + 64);
                const float w3 = __ldg(wr + 96);
                if (e & (1 << 16)) {
                    ab0 += val * w0; ab1 += val * w1; ab2 += val * w2; ab3 += val * w3;
                } else {
                    aw0 += val * w0; aw1 += val * w1; aw2 += val * w2; aw3 += val * w3;
                }
            }
            aw0 += __ldg(&b_ft[lane]);       ab0 += __ldg(&b_ft[lane]);
            aw1 += __ldg(&b_ft[lane + 32]);  ab1 += __ldg(&b_ft[lane + 32]);
            aw2 += __ldg(&b_ft[lane + 64]);  ab2 += __ldg(&b_ft[lane + 64]);
            aw3 += __ldg(&b_ft[lane + 96]);  ab3 += __ldg(&b_ft[lane + 96]);

            const float uu = __ldg(&us[row]);
            const float tt = __ldg(&them[row]);
            s_l0[lane]             = clip01(uu * aw0 + tt * ab0);
            s_l0[lane + 32]        = clip01(uu * aw1 + tt * ab1);
            s_l0[lane + 64]        = clip01(uu * aw2 + tt * ab2);
            s_l0[lane + 96]        = clip01(uu * aw3 + tt * ab3);
            s_l0[NL1 + lane]       = clip01(uu * ab0 + tt * aw0);
            s_l0[NL1 + lane + 32]  = clip01(uu * ab1 + tt * aw1);
            s_l0[NL1 + lane + 64]  = clip01(uu * ab2 + tt * aw2);
            s_l0[NL1 + lane + 96]  = clip01(uu * ab3 + tt * aw3);
            __syncwarp();

            float a1 = __ldg(&b1[lane]);
            #pragma unroll 8
            for (int ii = 0; ii < 2 * NL1; ++ii)
                a1 += s_l0[ii] * __ldg(&W1[ii * NL2 + lane]);
            const float l1v = clip01(a1);
            __syncwarp();

            float a2 = __ldg(&b2[lane]);
            #pragma unroll
            for (int ii = 0; ii < NL2; ++ii) {
                const float li = __shfl_sync(0xffffffffu, l1v, ii);
                a2 += li * __ldg(&W2[ii * NL2 + lane]);
            }
            const float l2v = clip01(a2);

            float r = l2v * __ldg(&Wo[lane]);
            #pragma unroll
            for (int off = 16; off > 0; off >>= 1)
                r += __shfl_down_sync(0xffffffffu, r, off);
            if (lane == 0) out[row] = r + __ldg(&bo[0]);
        }
    }
}

extern "C" void kernel_launch(void* const* d_in, const int* in_sizes, int n_in,
                              void* d_out, int out_size) {
    const float* us   = (const float*)d_in[0];
    const float* them = (const float*)d_in[1];
    const float* w_in = (const float*)d_in[2];
    const float* b_in = (const float*)d_in[3];
    const float* W_ft = (const float*)d_in[4];
    const float* b_ft = (const float*)d_in[5];
    const float* W1   = (const float*)d_in[6];
    const float* b1   = (const float*)d_in[7];
    const float* W2   = (const float*)d_in[8];
    const float* b2   = (const float*)d_in[9];
    const float* Wo   = (const float*)d_in[10];
    const float* bo   = (const float*)d_in[11];
    float* out = (float*)d_out;

    nnue_tma2_kernel<<<NBLK, NT>>>(us, them, w_in, b_in, W_ft, b_ft,
                                   W1, b1, W2, b2, Wo, bo, out);
}

// round 17
// speedup vs baseline: 1.1403x; 1.1403x over previous
#include <cuda_runtime.h>
#include <cuda_bf16.h>
#include <cstdint>

#define NB       4096
#define NINPUTS  41024
#define N4       (NINPUTS / 4)     // 10256 float4 per perspective row
#define TOT4     (2 * N4)          // 20512 fused (w then b)
#define NL1      128
#define NL2      32
#define CAPS     160               // entries per fused row (mean 60, +13 sigma)
#define LISTROWS 12                // buffered rows per block before flush
#define NT       256
#define U        8                 // float4 loads in flight per thread
#define NBLK     740               // 148 SMs * 5 resident blocks

__device__ int g_row;              // next unclaimed row

__global__ void init_kernel() {
    if (threadIdx.x == 0) g_row = NBLK;
}

__device__ __forceinline__ float clip01(float x) {
    return fminf(fmaxf(x, 0.f), 1.f);
}

// Warp-level MLP for one buffered row (lists in SMEM). noinline keeps its
// registers/code out of the hot scan loop (protects the 48-reg scan budget).
__device__ __noinline__ void do_mlp(
    int row, int cnt, const int* se, const float* sv, int lane, float* s_l0w,
    const float* __restrict__ us,   const float* __restrict__ them,
    const float* __restrict__ W_ft, const float* __restrict__ b_ft,
    const float* __restrict__ W1,   const float* __restrict__ b1,
    const float* __restrict__ W2,   const float* __restrict__ b2,
    const float* __restrict__ Wo,   const float* __restrict__ bo,
    float* __restrict__ out)
{
    // Gather: lane owns dims lane, lane+32, lane+64, lane+96.
    float aw0 = 0.f, aw1 = 0.f, aw2 = 0.f, aw3 = 0.f;
    float ab0 = 0.f, ab1 = 0.f, ab2 = 0.f, ab3 = 0.f;
    #pragma unroll 4
    for (int f = 0; f < cnt; ++f) {
        const int   e   = se[f];
        const float val = sv[f];
        const float* wr = W_ft + (e & 0xFFFF) * NL1 + lane;
        const float w0 = __ldg(wr);
        const float w1 = __ldg(wr + 32);
        const float w2 = __ldg(wr + 64);
        const float w3 = __ldg(wr + 96);
        if (e & (1 << 16)) {
            ab0 += val * w0; ab1 += val * w1; ab2 += val * w2; ab3 += val * w3;
        } else {
            aw0 += val * w0; aw1 += val * w1; aw2 += val * w2; aw3 += val * w3;
        }
    }
    aw0 += __ldg(&b_ft[lane]);       ab0 += __ldg(&b_ft[lane]);
    aw1 += __ldg(&b_ft[lane + 32]);  ab1 += __ldg(&b_ft[lane + 32]);
    aw2 += __ldg(&b_ft[lane + 64]);  ab2 += __ldg(&b_ft[lane + 64]);
    aw3 += __ldg(&b_ft[lane + 96]);  ab3 += __ldg(&b_ft[lane + 96]);

    const float uu = __ldg(&us[row]);
    const float tt = __ldg(&them[row]);
    s_l0w[lane]             = clip01(uu * aw0 + tt * ab0);
    s_l0w[lane + 32]        = clip01(uu * aw1 + tt * ab1);
    s_l0w[lane + 64]        = clip01(uu * aw2 + tt * ab2);
    s_l0w[lane + 96]        = clip01(uu * aw3 + tt * ab3);
    s_l0w[NL1 + lane]       = clip01(uu * ab0 + tt * aw0);
    s_l0w[NL1 + lane + 32]  = clip01(uu * ab1 + tt * aw1);
    s_l0w[NL1 + lane + 64]  = clip01(uu * ab2 + tt * aw2);
    s_l0w[NL1 + lane + 96]  = clip01(uu * ab3 + tt * aw3);
    __syncwarp();

    float a1 = __ldg(&b1[lane]);
    #pragma unroll 8
    for (int i = 0; i < 2 * NL1; ++i)
        a1 += s_l0w[i] * __ldg(&W1[i * NL2 + lane]);
    const float l1v = clip01(a1);
    __syncwarp();

    float a2 = __ldg(&b2[lane]);
    #pragma unroll
    for (int i = 0; i < NL2; ++i) {
        const float li = __shfl_sync(0xffffffffu, l1v, i);
        a2 += li * __ldg(&W2[i * NL2 + lane]);
    }
    const float l2v = clip01(a2);

    float r = l2v * __ldg(&Wo[lane]);
    #pragma unroll
    for (int off = 16; off > 0; off >>= 1)
        r += __shfl_down_sync(0xffffffffu, r, off);
    if (lane == 0) out[row] = r + __ldg(&bo[0]);
}

// All-warps-scan persistent kernel with deferred batched MLPs:
// every warp scans (40 scan-warps/SM = R3's proven 90% regime); each row's
// compaction list lands in its own SMEM slot; when LISTROWS slots fill (or
// rows run out) all 8 warps flush, one warp-level MLP per stored row. Rows
// claimed dynamically (one prefetched ATOMG per row, hidden under the ~59k-cyc
// row scan) to kill the ragged-tail loss. Hot loop: zero global fences.
__global__ void __launch_bounds__(NT, 5) nnue_scan_kernel(
    const float* __restrict__ us,   const float* __restrict__ them,
    const float* __restrict__ w_in, const float* __restrict__ b_in,
    const float* __restrict__ W_ft, const float* __restrict__ b_ft,
    const float* __restrict__ W1,   const float* __restrict__ b1,
    const float* __restrict__ W2,   const float* __restrict__ b2,
    const float* __restrict__ Wo,   const float* __restrict__ bo,
    float* __restrict__ out)
{
    __shared__ int   s_rows[2];          // current / prefetched row
    __shared__ int   s_myrow[LISTROWS];
    __shared__ int   s_cnt[LISTROWS];
    __shared__ int   s_e[LISTROWS][CAPS];   // (p<<16) | feature index
    __shared__ float s_v[LISTROWS][CAPS];
    __shared__ float s_l0[8][2 * NL1];   // per-warp MLP buffer

    const int tid  = threadIdx.x;
    const int lane = tid & 31;
    const int warp = tid >> 5;

    if (tid == 0) s_rows[0] = blockIdx.x;
    if (tid < LISTROWS) s_cnt[tid] = 0;
    __syncthreads();

    int li = 0;
    for (int k = 0; ; ++k) {
        const int row = s_rows[k & 1];
        if (row >= NB) break;

        // prefetch next row claim (ATOMG hidden under this row's ~59k-cyc scan)
        if (tid == 0) {
            s_rows[(k + 1) & 1] = atomicAdd(&g_row, 1);
            s_myrow[li] = row;
        }

        // ---- scan both perspective rows into list slot li ----
        const float4* __restrict__ w4 = (const float4*)(w_in + (size_t)row * NINPUTS);
        const float4* __restrict__ b4 = (const float4*)(b_in + (size_t)row * NINPUTS);
        int* se = &s_e[li][0];
        float* sv = &s_v[li][0];
        int* sc = &s_cnt[li];

        #pragma unroll 1
        for (int base = 0; base < TOT4; base += NT * U) {
            float4 v[U];
            #pragma unroll
            for (int u = 0; u < U; ++u) {
                const int i = base + u * NT + tid;
                if (i < TOT4) {
                    const float4* p4 = (i < N4) ? (w4 + i) : (b4 + (i - N4));
                    v[u] = __ldcs(p4);       // evict-first: keep W_ft in L2
                } else {
                    v[u] = make_float4(0.f, 0.f, 0.f, 0.f);
                }
            }
            #pragma unroll
            for (int u = 0; u < U; ++u) {
                // integer zero tests: mask values are {0.0f, 1.0f}
                const int ix = __float_as_int(v[u].x);
                const int iy = __float_as_int(v[u].y);
                const int iz = __float_as_int(v[u].z);
                const int iw = __float_as_int(v[u].w);
                if ((ix | iy | iz | iw) != 0) {
                    const int i   = base + u * NT + tid;
                    const int p   = (i >= N4);
                    const int col = (i - p * N4) * 4;
                    const int tag = p << 16;
                    if (ix) { int q = atomicAdd(sc, 1); if (q < CAPS) { se[q] = tag | (col + 0); sv[q] = v[u].x; } }
                    if (iy) { int q = atomicAdd(sc, 1); if (q < CAPS) { se[q] = tag | (col + 1); sv[q] = v[u].y; } }
                    if (iz) { int q = atomicAdd(sc, 1); if (q < CAPS) { se[q] = tag | (col + 2); sv[q] = v[u].z; } }
                    if (iw) { int q = atomicAdd(sc, 1); if (q < CAPS) { se[q] = tag | (col + 3); sv[q] = v[u].w; } }
                }
            }
        }

        ++li;
        __syncthreads();   // list li-1 complete; s_rows[(k+1)&1] visible

        if (li == LISTROWS) {
            // ---- flush: warp w MLPs stored rows w, w+8, ... ----
            for (int r = warp; r < LISTROWS; r += 8)
                do_mlp(s_myrow[r], min(s_cnt[r], CAPS), &s_e[r][0], &s_v[r][0],
                       lane, &s_l0[warp][0],
                       us, them, W_ft, b_ft, W1, b1, W2, b2, Wo, bo, out);
            __syncthreads();
            if (tid < LISTROWS) s_cnt[tid] = 0;
            li = 0;
            __syncthreads();
        }
    }

    // ---- final flush ----
    __syncthreads();
    for (int r = warp; r < li; r += 8)
        do_mlp(s_myrow[r], min(s_cnt[r], CAPS), &s_e[r][0], &s_v[r][0],
               lane, &s_l0[warp][0],
               us, them, W_ft, b_ft, W1, b1, W2, b2, Wo, bo, out);
}

extern "C" void kernel_launch(void* const* d_in, const int* in_sizes, int n_in,
                              void* d_out, int out_size) {
    const float* us   = (const float*)d_in[0];
    const float* them = (const float*)d_in[1];
    const float* w_in = (const float*)d_in[2];
    const float* b_in = (const float*)d_in[3];
    const float* W_ft = (const float*)d_in[4];
    const float* b_ft = (const float*)d_in[5];
    const float* W1   = (const float*)d_in[6];
    const float* b1   = (const float*)d_in[7];
    const float* W2   = (const float*)d_in[8];
    const float* b2   = (const float*)d_in[9];
    const float* Wo   = (const float*)d_in[10];
    const float* bo   = (const float*)d_in[11];
    float* out = (float*)d_out;

    init_kernel<<<1, 32>>>();
    nnue_scan_kernel<<<NBLK, NT>>>(us, them, w_in, b_in, W_ft, b_ft,
                                   W1, b1, W2, b2, Wo, bo, out);
}